// round 16
// baseline (speedup 1.0000x reference)
#include <cuda_runtime.h>
#include <cuda_bf16.h>
#include <cstdint>
#include <math.h>

#define N_TOK   8192
#define DMODEL  1024
#define QKVD    3072
#define KVW     2048    // K|V packed width (bf16 split storage)
#define NHEAD   16
#define DHEAD   64
#define NEXP    8
#define HFF     4096
#define TSEQ    1024
#define BATCH   8
#define NLAYER  2
#define CAP     17408   // 16384 assignments + 8*128 alignment pad

// ---------------- device scratch ----------------
__device__ float g_x[N_TOK*DMODEL];
__device__ float g_qkv[(size_t)N_TOK*QKVD];          // only Q cols [0,1024) used by attn
__device__ __nv_bfloat16 g_kvh[(size_t)N_TOK*KVW];   // K|V hi (split once in GEMM-0 epilogue)
__device__ __nv_bfloat16 g_kvl[(size_t)N_TOK*KVW];   // K|V lo
__device__ float g_h[N_TOK*DMODEL];
__device__ float g_tmp[N_TOK*DMODEL];
__device__ float g_eout[(size_t)CAP*DMODEL];         // per-slot weighted expert output
__device__ float g_h1[(size_t)CAP*HFF];
__device__ float g_probs[N_TOK*NEXP];
__device__ int   g_tki[N_TOK*2];
__device__ float g_tkw[N_TOK*2];
__device__ int   g_slot[N_TOK*2];                    // token -> slot map
__device__ int   g_counts[NEXP];
__device__ int   g_cursor[NEXP];
__device__ int   g_off[NEXP+1];
__device__ int   g_atok[CAP];
__device__ float g_aw[CAP];
__device__ float g_Pc[NEXP];
__device__ float g_lb;

// ---------------- reductions ----------------
__device__ __forceinline__ float warpRedSum(float v){
#pragma unroll
    for (int o = 16; o; o >>= 1) v += __shfl_xor_sync(0xffffffffu, v, o);
    return v;
}
__device__ float blockRedSum(float v, float* red){
    int lane = threadIdx.x & 31, w = threadIdx.x >> 5, nw = blockDim.x >> 5;
    __syncthreads();
    v = warpRedSum(v);
    if (lane == 0) red[w] = v;
    __syncthreads();
    if (w == 0){
        float x = (lane < nw) ? red[lane] : 0.f;
        x = warpRedSum(x);
        if (lane == 0) red[0] = x;
    }
    __syncthreads();
    return red[0];
}

// ---------------- bf16 helpers (round-nearest split) ----------------
__device__ __forceinline__ unsigned hi2u(float a, float b){
    __nv_bfloat162 h(__float2bfloat16(a), __float2bfloat16(b));
    return *(unsigned*)&h;
}
__device__ __forceinline__ unsigned lo2u(float a, float b){
    float ha = __bfloat162float(__float2bfloat16(a));
    float hb = __bfloat162float(__float2bfloat16(b));
    __nv_bfloat162 l(__float2bfloat16(a - ha), __float2bfloat16(b - hb));
    return *(unsigned*)&l;
}
__device__ __forceinline__ void mma_bf16(float c[4], const unsigned a[4],
                                         unsigned b0, unsigned b1){
    asm volatile("mma.sync.aligned.m16n8k16.row.col.f32.bf16.bf16.f32 "
        "{%0,%1,%2,%3}, {%4,%5,%6,%7}, {%8,%9}, {%0,%1,%2,%3};"
        : "+f"(c[0]), "+f"(c[1]), "+f"(c[2]), "+f"(c[3])
        : "r"(a[0]), "r"(a[1]), "r"(a[2]), "r"(a[3]), "r"(b0), "r"(b1));
}
__device__ __forceinline__ void ldsm4(unsigned r[4], const __nv_bfloat16* p){
    unsigned addr = (unsigned)__cvta_generic_to_shared((void*)p);
    asm volatile("ldmatrix.sync.aligned.m8n8.x4.shared.b16 {%0,%1,%2,%3}, [%4];"
        : "=r"(r[0]), "=r"(r[1]), "=r"(r[2]), "=r"(r[3]) : "r"(addr));
}
__device__ __forceinline__ void ldsm4t(unsigned r[4], const __nv_bfloat16* p){
    unsigned addr = (unsigned)__cvta_generic_to_shared((void*)p);
    asm volatile("ldmatrix.sync.aligned.m8n8.x4.trans.shared.b16 {%0,%1,%2,%3}, [%4];"
        : "=r"(r[0]), "=r"(r[1]), "=r"(r[2]), "=r"(r[3]) : "r"(addr));
}

// ---------------- embedding + positional ----------------
__global__ void embed_kernel(const int* __restrict__ ids,
                             const float* __restrict__ emb,
                             const float* __restrict__ pos){
    int n = blockIdx.x, tid = threadIdx.x;
    int t = n & (TSEQ - 1);
    int id = ids[n];
#pragma unroll
    for (int i = 0; i < 4; i++){
        int d = tid + i * 256;
        g_x[(size_t)n*DMODEL + d] = emb[(size_t)id*DMODEL + d] + pos[(size_t)t*DMODEL + d];
    }
}

// ------- bf16x3 split-fp32 tensor-core GEMM, 128x128 tile, BK=16 -------
// MODE 0: Q (fp32) + K/V (bf16 hi/lo split) = x @ Wqkv + b
// MODE 1: g_tmp = h @ Wo + b
// MODE 2: g_h1  = relu(gather(x) @ W1[e]+b1[e])
// MODE 3: g_eout[slot] = w_slot * (g_h1 @ W2[e] + b2[e])   (plain stores)
#define APAD 24
#define BPAD 136
template<int MODE>
__global__ void __launch_bounds__(256, 2)
mma_gemm(const float* __restrict__ Bmat, const float* __restrict__ biasB,
         int N, int K)
{
    int bn = blockIdx.x * 128;
    int bm = blockIdx.y * 128;
    int tid  = threadIdx.x;
    int warp = tid >> 5, lane = tid & 31;
    int wm = warp >> 1, wn = warp & 1;

    int e = 0;
    if (MODE == 2 || MODE == 3){
        if (bm >= g_off[NEXP]) return;
#pragma unroll
        for (int i = 1; i < NEXP; i++) if (bm >= g_off[i]) e = i;
        Bmat  += (size_t)e * K * N;
        biasB += (size_t)e * N;
    }

    __shared__ __align__(16) __nv_bfloat16 Ah[2][128][APAD];
    __shared__ __align__(16) __nv_bfloat16 Al[2][128][APAD];
    __shared__ __align__(16) __nv_bfloat16 Bh[2][16][BPAD];
    __shared__ __align__(16) __nv_bfloat16 Bl[2][16][BPAD];

    int r0 = tid >> 2, r1 = r0 + 64;
    int k4 = (tid & 3) * 4;
    int kb0 = tid >> 5, kb1 = kb0 + 8;
    int cb  = (tid & 31) * 4;

    const float *Ap0, *Ap1;
    if      (MODE == 0){ Ap0 = &g_x [(size_t)(bm + r0) * DMODEL]; Ap1 = &g_x [(size_t)(bm + r1) * DMODEL]; }
    else if (MODE == 1){ Ap0 = &g_h [(size_t)(bm + r0) * DMODEL]; Ap1 = &g_h [(size_t)(bm + r1) * DMODEL]; }
    else if (MODE == 2){ Ap0 = &g_x [(size_t)g_atok[bm + r0] * DMODEL]; Ap1 = &g_x [(size_t)g_atok[bm + r1] * DMODEL]; }
    else               { Ap0 = &g_h1[(size_t)(bm + r0) * HFF];    Ap1 = &g_h1[(size_t)(bm + r1) * HFF]; }

    const float* Bp0 = Bmat + (size_t)kb0 * N + bn + cb;
    const float* Bp1 = Bmat + (size_t)kb1 * N + bn + cb;

    float acc[2][8][4];
#pragma unroll
    for (int mt = 0; mt < 2; mt++)
#pragma unroll
        for (int nt = 0; nt < 8; nt++)
#pragma unroll
            for (int i = 0; i < 4; i++) acc[mt][nt][i] = 0.f;

    float4 pa0 = *(const float4*)(Ap0 + k4);
    float4 pa1 = *(const float4*)(Ap1 + k4);
    float4 pb0 = *(const float4*)Bp0;
    float4 pb1 = *(const float4*)Bp1;

    {
        *(uint2*)&Ah[0][r0][k4] = make_uint2(hi2u(pa0.x,pa0.y), hi2u(pa0.z,pa0.w));
        *(uint2*)&Al[0][r0][k4] = make_uint2(lo2u(pa0.x,pa0.y), lo2u(pa0.z,pa0.w));
        *(uint2*)&Ah[0][r1][k4] = make_uint2(hi2u(pa1.x,pa1.y), hi2u(pa1.z,pa1.w));
        *(uint2*)&Al[0][r1][k4] = make_uint2(lo2u(pa1.x,pa1.y), lo2u(pa1.z,pa1.w));
        *(uint2*)&Bh[0][kb0][cb] = make_uint2(hi2u(pb0.x,pb0.y), hi2u(pb0.z,pb0.w));
        *(uint2*)&Bl[0][kb0][cb] = make_uint2(lo2u(pb0.x,pb0.y), lo2u(pb0.z,pb0.w));
        *(uint2*)&Bh[0][kb1][cb] = make_uint2(hi2u(pb1.x,pb1.y), hi2u(pb1.z,pb1.w));
        *(uint2*)&Bl[0][kb1][cb] = make_uint2(lo2u(pb1.x,pb1.y), lo2u(pb1.z,pb1.w));
    }
    __syncthreads();

    int arow = (lane & 15), akc = (lane >> 4) * 8;
    int bkr  = (lane & 7) + ((lane >> 3) & 1) * 8;
    int bnc  = wn * 64 + (lane >> 4) * 8;

    int buf = 0;
    for (int k0 = 0; k0 < K; k0 += 16){
        bool more = (k0 + 16 < K);
        if (more){
            pa0 = *(const float4*)(Ap0 + k0 + 16 + k4);
            pa1 = *(const float4*)(Ap1 + k0 + 16 + k4);
            pb0 = *(const float4*)(Bp0 + (size_t)16 * N);
            pb1 = *(const float4*)(Bp1 + (size_t)16 * N);
            Bp0 += (size_t)16 * N; Bp1 += (size_t)16 * N;
        }

        unsigned ah[2][4], al[2][4];
#pragma unroll
        for (int mt = 0; mt < 2; mt++){
            int r = wm*32 + mt*16 + arow;
            ldsm4(ah[mt], &Ah[buf][r][akc]);
            ldsm4(al[mt], &Al[buf][r][akc]);
        }
#pragma unroll
        for (int ng = 0; ng < 4; ng++){
            unsigned bh[4], bl[4];
            ldsm4t(bh, &Bh[buf][bkr][bnc + ng*16]);
            ldsm4t(bl, &Bl[buf][bkr][bnc + ng*16]);
#pragma unroll
            for (int mt = 0; mt < 2; mt++){
                mma_bf16(acc[mt][2*ng  ], ah[mt], bh[0], bh[1]);
                mma_bf16(acc[mt][2*ng  ], ah[mt], bl[0], bl[1]);
                mma_bf16(acc[mt][2*ng  ], al[mt], bh[0], bh[1]);
                mma_bf16(acc[mt][2*ng+1], ah[mt], bh[2], bh[3]);
                mma_bf16(acc[mt][2*ng+1], ah[mt], bl[2], bl[3]);
                mma_bf16(acc[mt][2*ng+1], al[mt], bh[2], bh[3]);
            }
        }

        if (more){
            int nb = buf ^ 1;
            *(uint2*)&Ah[nb][r0][k4] = make_uint2(hi2u(pa0.x,pa0.y), hi2u(pa0.z,pa0.w));
            *(uint2*)&Al[nb][r0][k4] = make_uint2(lo2u(pa0.x,pa0.y), lo2u(pa0.z,pa0.w));
            *(uint2*)&Ah[nb][r1][k4] = make_uint2(hi2u(pa1.x,pa1.y), hi2u(pa1.z,pa1.w));
            *(uint2*)&Al[nb][r1][k4] = make_uint2(lo2u(pa1.x,pa1.y), lo2u(pa1.z,pa1.w));
            *(uint2*)&Bh[nb][kb0][cb] = make_uint2(hi2u(pb0.x,pb0.y), hi2u(pb0.z,pb0.w));
            *(uint2*)&Bl[nb][kb0][cb] = make_uint2(lo2u(pb0.x,pb0.y), lo2u(pb0.z,pb0.w));
            *(uint2*)&Bh[nb][kb1][cb] = make_uint2(hi2u(pb1.x,pb1.y), hi2u(pb1.z,pb1.w));
            *(uint2*)&Bl[nb][kb1][cb] = make_uint2(lo2u(pb1.x,pb1.y), lo2u(pb1.z,pb1.w));
        }
        __syncthreads();
        buf ^= 1;
    }

    int rql = lane >> 2, rqm = lane & 3;
    int c_lo = 2 * rqm;
#pragma unroll
    for (int mt = 0; mt < 2; mt++){
        int grA = bm + wm*32 + mt*16 + rql;
        int grB = grA + 8;
        if (MODE == 3){
            float wA = g_aw[grA], wB = g_aw[grB];
#pragma unroll
            for (int nt = 0; nt < 8; nt++){
                int gc = bn + wn*64 + nt*8 + c_lo;
                float b0 = biasB[gc], b1 = biasB[gc+1];
                *(float2*)&g_eout[(size_t)grA*DMODEL + gc] =
                    make_float2(wA*(acc[mt][nt][0] + b0), wA*(acc[mt][nt][1] + b1));
                *(float2*)&g_eout[(size_t)grB*DMODEL + gc] =
                    make_float2(wB*(acc[mt][nt][2] + b0), wB*(acc[mt][nt][3] + b1));
            }
        } else {
#pragma unroll
            for (int nt = 0; nt < 8; nt++){
                int gc = bn + wn*64 + nt*8 + c_lo;
                float b0 = biasB[gc], b1 = biasB[gc+1];
                float v0 = acc[mt][nt][0] + b0, v1 = acc[mt][nt][1] + b1;
                float v2 = acc[mt][nt][2] + b0, v3 = acc[mt][nt][3] + b1;
                if (MODE == 0){
                    if (gc < DMODEL){   // Q stays fp32
                        g_qkv[(size_t)grA*QKVD + gc] = v0; g_qkv[(size_t)grA*QKVD + gc+1] = v1;
                        g_qkv[(size_t)grB*QKVD + gc] = v2; g_qkv[(size_t)grB*QKVD + gc+1] = v3;
                    } else {            // K/V: split once, store bf16 hi/lo
                        size_t iA = (size_t)grA*KVW + (gc - DMODEL);
                        size_t iB = (size_t)grB*KVW + (gc - DMODEL);
                        *(unsigned*)&g_kvh[iA] = hi2u(v0, v1);
                        *(unsigned*)&g_kvl[iA] = lo2u(v0, v1);
                        *(unsigned*)&g_kvh[iB] = hi2u(v2, v3);
                        *(unsigned*)&g_kvl[iB] = lo2u(v2, v3);
                    }
                } else if (MODE == 1){
                    g_tmp[(size_t)grA*DMODEL + gc] = v0; g_tmp[(size_t)grA*DMODEL + gc+1] = v1;
                    g_tmp[(size_t)grB*DMODEL + gc] = v2; g_tmp[(size_t)grB*DMODEL + gc+1] = v3;
                } else {
                    g_h1[(size_t)grA*HFF + gc]   = fmaxf(v0, 0.f);
                    g_h1[(size_t)grA*HFF + gc+1] = fmaxf(v1, 0.f);
                    g_h1[(size_t)grB*HFF + gc]   = fmaxf(v2, 0.f);
                    g_h1[(size_t)grB*HFF + gc+1] = fmaxf(v3, 0.f);
                }
            }
        }
    }
}

// -------- tensor-core flash attention (bf16x3), 64q x 64k tiles --------
// K/V pre-split by GEMM-0 epilogue: staging is pure uint4 copies.
__global__ void __launch_bounds__(128)
attn_mma_kernel(const int* __restrict__ amask){
    int qt = gridDim.x - 1 - blockIdx.x;   // big blocks first
    int h = blockIdx.y, b = blockIdx.z;
    int tid = threadIdx.x, warp = tid >> 5, lane = tid & 31;
    int g = lane >> 2, q = lane & 3;
    int qbase = qt * 64;

    __shared__ __align__(16) __nv_bfloat16 Kh[64][72], Kl[64][72];
    __shared__ __align__(16) __nv_bfloat16 Vh[64][72], Vl[64][72];
    __shared__ int AMs[64];

    {
        int row = tid >> 1, c0 = (tid & 1) * 32;
        const float* src = &g_qkv[(size_t)(b*TSEQ + qbase + row)*QKVD + h*DHEAD + c0];
#pragma unroll
        for (int i = 0; i < 8; i++){
            float4 v = *(const float4*)(src + i*4);
            v.x *= 0.125f; v.y *= 0.125f; v.z *= 0.125f; v.w *= 0.125f;
            *(uint2*)&Kh[row][c0 + i*4] = make_uint2(hi2u(v.x,v.y), hi2u(v.z,v.w));
            *(uint2*)&Kl[row][c0 + i*4] = make_uint2(lo2u(v.x,v.y), lo2u(v.z,v.w));
        }
    }
    __syncthreads();

    unsigned qhf[4][4], qlf[4][4];
    {
        int r = warp*16 + (lane & 15);
        int kc = (lane >> 4) * 8;
#pragma unroll
        for (int kk = 0; kk < 4; kk++){
            ldsm4(qhf[kk], &Kh[r][kk*16 + kc]);
            ldsm4(qlf[kk], &Kl[r][kk*16 + kc]);
        }
    }

    float o[8][4];
#pragma unroll
    for (int i = 0; i < 8; i++)
#pragma unroll
        for (int j = 0; j < 4; j++) o[i][j] = 0.f;
    float m0 = -3.0e38f, m1 = -3.0e38f, l0 = 0.f, l1 = 0.f;

    int row0 = qbase + warp*16 + g, row1 = row0 + 8;
    int nrow = lane & 15, nkc = (lane >> 4) * 8;
    int bkr  = (lane & 7) + ((lane >> 3) & 1) * 8;
    int bnc  = (lane >> 4) * 8;

    int ntiles = qt + 1;
    for (int tile = 0; tile < ntiles; tile++){
        int j0 = tile * 64;
        __syncthreads();
        {
            int row = tid >> 1, c0 = (tid & 1) * 32;
            size_t base = (size_t)(b*TSEQ + j0 + row)*KVW + h*DHEAD + c0;
#pragma unroll
            for (int i = 0; i < 4; i++){
                *(uint4*)&Kh[row][c0+i*8] = *(const uint4*)&g_kvh[base + i*8];
                *(uint4*)&Kl[row][c0+i*8] = *(const uint4*)&g_kvl[base + i*8];
                *(uint4*)&Vh[row][c0+i*8] = *(const uint4*)&g_kvh[base + DMODEL + i*8];
                *(uint4*)&Vl[row][c0+i*8] = *(const uint4*)&g_kvl[base + DMODEL + i*8];
            }
            if (tid < 64) AMs[tid] = amask[b*TSEQ + j0 + tid];
        }
        __syncthreads();

        float st[8][4];
#pragma unroll
        for (int i = 0; i < 8; i++)
#pragma unroll
            for (int j = 0; j < 4; j++) st[i][j] = 0.f;
#pragma unroll
        for (int nt2 = 0; nt2 < 4; nt2++){
#pragma unroll
            for (int kk = 0; kk < 4; kk++){
                unsigned kh[4], kl[4];
                ldsm4(kh, &Kh[nt2*16 + nrow][kk*16 + nkc]);
                ldsm4(kl, &Kl[nt2*16 + nrow][kk*16 + nkc]);
                mma_bf16(st[2*nt2  ], qhf[kk], kh[0], kh[2]);
                mma_bf16(st[2*nt2  ], qhf[kk], kl[0], kl[2]);
                mma_bf16(st[2*nt2  ], qlf[kk], kh[0], kh[2]);
                mma_bf16(st[2*nt2+1], qhf[kk], kh[1], kh[3]);
                mma_bf16(st[2*nt2+1], qhf[kk], kl[1], kl[3]);
                mma_bf16(st[2*nt2+1], qlf[kk], kh[1], kh[3]);
            }
        }

#pragma unroll
        for (int nt = 0; nt < 8; nt++){
            int lc = nt*8 + 2*q;
            int c  = j0 + lc;
            int a0 = AMs[lc], a1 = AMs[lc+1];
            if (c   > row0 || !a0) st[nt][0] = -1e9f;
            if (c+1 > row0 || !a1) st[nt][1] = -1e9f;
            if (c   > row1 || !a0) st[nt][2] = -1e9f;
            if (c+1 > row1 || !a1) st[nt][3] = -1e9f;
        }

        float mx0 = -3.0e38f, mx1 = -3.0e38f;
#pragma unroll
        for (int nt = 0; nt < 8; nt++){
            mx0 = fmaxf(mx0, fmaxf(st[nt][0], st[nt][1]));
            mx1 = fmaxf(mx1, fmaxf(st[nt][2], st[nt][3]));
        }
#pragma unroll
        for (int off = 1; off <= 2; off <<= 1){
            mx0 = fmaxf(mx0, __shfl_xor_sync(0xffffffffu, mx0, off));
            mx1 = fmaxf(mx1, __shfl_xor_sync(0xffffffffu, mx1, off));
        }
        float mn0 = fmaxf(m0, mx0), mn1 = fmaxf(m1, mx1);
        float sc0 = __expf(m0 - mn0), sc1 = __expf(m1 - mn1);
        float ls0 = 0.f, ls1 = 0.f;
#pragma unroll
        for (int nt = 0; nt < 8; nt++){
            st[nt][0] = __expf(st[nt][0] - mn0);
            st[nt][1] = __expf(st[nt][1] - mn0);
            st[nt][2] = __expf(st[nt][2] - mn1);
            st[nt][3] = __expf(st[nt][3] - mn1);
            ls0 += st[nt][0] + st[nt][1];
            ls1 += st[nt][2] + st[nt][3];
        }
#pragma unroll
        for (int off = 1; off <= 2; off <<= 1){
            ls0 += __shfl_xor_sync(0xffffffffu, ls0, off);
            ls1 += __shfl_xor_sync(0xffffffffu, ls1, off);
        }
        l0 = l0*sc0 + ls0;  l1 = l1*sc1 + ls1;
#pragma unroll
        for (int nt = 0; nt < 8; nt++){
            o[nt][0] *= sc0; o[nt][1] *= sc0;
            o[nt][2] *= sc1; o[nt][3] *= sc1;
        }
        m0 = mn0; m1 = mn1;

#pragma unroll
        for (int kk2 = 0; kk2 < 4; kk2++){
            unsigned ph[4], pl[4];
            ph[0] = hi2u(st[2*kk2  ][0], st[2*kk2  ][1]);
            ph[1] = hi2u(st[2*kk2  ][2], st[2*kk2  ][3]);
            ph[2] = hi2u(st[2*kk2+1][0], st[2*kk2+1][1]);
            ph[3] = hi2u(st[2*kk2+1][2], st[2*kk2+1][3]);
            pl[0] = lo2u(st[2*kk2  ][0], st[2*kk2  ][1]);
            pl[1] = lo2u(st[2*kk2  ][2], st[2*kk2  ][3]);
            pl[2] = lo2u(st[2*kk2+1][0], st[2*kk2+1][1]);
            pl[3] = lo2u(st[2*kk2+1][2], st[2*kk2+1][3]);
#pragma unroll
            for (int dt2 = 0; dt2 < 4; dt2++){
                unsigned vh[4], vl[4];
                ldsm4t(vh, &Vh[kk2*16 + bkr][dt2*16 + bnc]);
                ldsm4t(vl, &Vl[kk2*16 + bkr][dt2*16 + bnc]);
                mma_bf16(o[2*dt2  ], ph, vh[0], vh[1]);
                mma_bf16(o[2*dt2  ], ph, vl[0], vl[1]);
                mma_bf16(o[2*dt2  ], pl, vh[0], vh[1]);
                mma_bf16(o[2*dt2+1], ph, vh[2], vh[3]);
                mma_bf16(o[2*dt2+1], ph, vl[2], vl[3]);
                mma_bf16(o[2*dt2+1], pl, vh[2], vh[3]);
            }
        }
    }

    float inv0 = 1.f / l0, inv1 = 1.f / l1;
    size_t n0 = (size_t)(b*TSEQ + row0)*DMODEL + h*DHEAD;
    size_t n1 = (size_t)(b*TSEQ + row1)*DMODEL + h*DHEAD;
#pragma unroll
    for (int dt = 0; dt < 8; dt++){
        int c = dt*8 + 2*q;
        *(float2*)&g_h[n0 + c] = make_float2(o[dt][0]*inv0, o[dt][1]*inv0);
        *(float2*)&g_h[n1 + c] = make_float2(o[dt][2]*inv1, o[dt][3]*inv1);
    }
}

// ------- fused: x = LN(x + g_tmp); then router (gate+softmax+top2) -------
__global__ void add_ln_gate_kernel(const float* __restrict__ g,
                                   const float* __restrict__ bta,
                                   const float* __restrict__ W,
                                   const float* __restrict__ bb){
    int n = blockIdx.x, tid = threadIdx.x;
    __shared__ float red[32];
    __shared__ float sred[NEXP][256];
    float v[4];
    float s = 0.f;
#pragma unroll
    for (int i = 0; i < 4; i++){
        int d = tid + i*256;
        v[i] = g_x[(size_t)n*DMODEL + d] + g_tmp[(size_t)n*DMODEL + d];
        s += v[i];
    }
    float mean = blockRedSum(s, red) * (1.f/DMODEL);
    float vs = 0.f;
#pragma unroll
    for (int i = 0; i < 4; i++){ float dd = v[i] - mean; vs += dd*dd; }
    float var = blockRedSum(vs, red) * (1.f/DMODEL);
    float r = rsqrtf(var + 1e-5f);
    float y[4];
#pragma unroll
    for (int i = 0; i < 4; i++){
        int d = tid + i*256;
        y[i] = (v[i] - mean)*r*g[d] + bta[d];
        g_x[(size_t)n*DMODEL + d] = y[i];
    }
    // ---- router on the registers we already hold ----
    float acc[NEXP];
#pragma unroll
    for (int e = 0; e < NEXP; e++) acc[e] = 0.f;
#pragma unroll
    for (int i = 0; i < 4; i++){
        int d = tid + i*256;
#pragma unroll
        for (int e = 0; e < NEXP; e++) acc[e] += y[i] * W[d*NEXP + e];
    }
#pragma unroll
    for (int e = 0; e < NEXP; e++) sred[e][tid] = acc[e];
    __syncthreads();
    for (int st = 128; st > 0; st >>= 1){
        if (tid < st){
#pragma unroll
            for (int e = 0; e < NEXP; e++) sred[e][tid] += sred[e][tid + st];
        }
        __syncthreads();
    }
    if (tid == 0){
        float lg[NEXP], mx = -3e38f;
#pragma unroll
        for (int e = 0; e < NEXP; e++){ lg[e] = sred[e][0] + bb[e]; mx = fmaxf(mx, lg[e]); }
        float ss = 0.f, p[NEXP];
#pragma unroll
        for (int e = 0; e < NEXP; e++){ p[e] = __expf(lg[e] - mx); ss += p[e]; }
        float invs = 1.f / ss;
#pragma unroll
        for (int e = 0; e < NEXP; e++){ p[e] *= invs; g_probs[n*NEXP + e] = p[e]; }
        int i1 = 0;
#pragma unroll
        for (int e = 1; e < NEXP; e++) if (p[e] > p[i1]) i1 = e;
        int i2 = (i1 == 0) ? 1 : 0;
#pragma unroll
        for (int e = 0; e < NEXP; e++) if (e != i1 && p[e] > p[i2]) i2 = e;
        float sw = p[i1] + p[i2];
        g_tki[n*2]   = i1; g_tki[n*2+1] = i2;
        g_tkw[n*2]   = p[i1] / sw;
        g_tkw[n*2+1] = p[i2] / sw;
        atomicAdd(&g_counts[i1], 1);
        atomicAdd(&g_counts[i2], 1);
    }
}

// ------- x = LN(x + gather2(g_eout)); optionally also write d_out -------
__global__ void add_ln2_kernel(const float* __restrict__ g,
                               const float* __restrict__ bta,
                               float* __restrict__ out){
    int n = blockIdx.x, tid = threadIdx.x;
    __shared__ float red[32];
    float v[4];
    float s = 0.f;
    size_t s0 = (size_t)g_slot[n*2]     * DMODEL;
    size_t s1 = (size_t)g_slot[n*2 + 1] * DMODEL;
#pragma unroll
    for (int i = 0; i < 4; i++){
        int d = tid + i*256;
        v[i] = g_x[(size_t)n*DMODEL + d] + (g_eout[s0 + d] + g_eout[s1 + d]);
        s += v[i];
    }
    float mean = blockRedSum(s, red) * (1.f/DMODEL);
    float vs = 0.f;
#pragma unroll
    for (int i = 0; i < 4; i++){ float dd = v[i] - mean; vs += dd*dd; }
    float var = blockRedSum(vs, red) * (1.f/DMODEL);
    float r = rsqrtf(var + 1e-5f);
#pragma unroll
    for (int i = 0; i < 4; i++){
        int d = tid + i*256;
        float val = (v[i] - mean)*r*g[d] + bta[d];
        size_t idx = (size_t)n*DMODEL + d;
        g_x[idx] = val;
        if (out) out[idx] = val;
    }
}

// ---------------- tiny per-layer reset (counts/cursor only) ----------------
__global__ void reset_counts_kernel(){
    int i = threadIdx.x;
    if (i < NEXP){ g_counts[i] = 0; g_cursor[i] = 0; }
}

__global__ void scan_kernel(){
    if (threadIdx.x == 0){
        int o = 0;
        for (int e = 0; e < NEXP; e++){
            g_off[e] = o;
            o += (g_counts[e] + 127) & ~127;
        }
        g_off[NEXP] = o;
    }
}

__global__ void scatter_kernel(){
    int n = blockIdx.x * blockDim.x + threadIdx.x;
    if (n >= N_TOK) return;
#pragma unroll
    for (int k = 0; k < 2; k++){
        int e = g_tki[n*2 + k];
        int pos = atomicAdd(&g_cursor[e], 1);
        int slot = g_off[e] + pos;
        g_atok[slot] = n;
        g_aw[slot]   = g_tkw[n*2 + k];
        g_slot[n*2 + k] = slot;
    }
}

// ---------------- load-balance loss ----------------
__global__ void lb_part_kernel(){
    int e = blockIdx.x, tid = threadIdx.x;
    __shared__ float red[32];
    float s = 0.f;
    for (int n = tid; n < N_TOK; n += 256) s += g_probs[n*NEXP + e];
    float tot = blockRedSum(s, red);
    if (tid == 0)
        g_Pc[e] = (float)NEXP * ((float)g_counts[e] / (float)N_TOK) * (tot / (float)N_TOK);
}
__global__ void lb_acc_kernel(){
    if (threadIdx.x == 0){
        float s = 0.f;
        for (int e = 0; e < NEXP; e++) s += g_Pc[e];
        g_lb += s;
    }
}
__global__ void init_kernel(){ g_lb = 0.f; }

// ---------------- output tail (lb scalar) / fallback full copy ----------------
__global__ void lb_tail_kernel(float* __restrict__ out, int out_size){
    int i = N_TOK*DMODEL + blockIdx.x * blockDim.x + threadIdx.x;
    if (i < out_size) out[i] = g_lb;
}
__global__ void finalize_kernel(float* __restrict__ out, int out_size){
    int i = blockIdx.x * blockDim.x + threadIdx.x;
    if (i >= out_size) return;
    if (i < N_TOK*DMODEL) out[i] = g_x[i];
    else                  out[i] = g_lb;
}

// ---------------- host orchestration ----------------
extern "C" void kernel_launch(void* const* d_in, const int* in_sizes, int n_in,
                              void* d_out, int out_size)
{
    const int*   ids  = (const int*)  d_in[0];
    const int*   am   = (const int*)  d_in[1];
    const float* emb  = (const float*)d_in[2];
    const float* pos  = (const float*)d_in[3];
    const float* Wqkv = (const float*)d_in[4];
    const float* bqkv = (const float*)d_in[5];
    const float* Wo   = (const float*)d_in[6];
    const float* bo   = (const float*)d_in[7];
    const float* ln1g = (const float*)d_in[8];
    const float* ln1b = (const float*)d_in[9];
    const float* ln2g = (const float*)d_in[10];
    const float* ln2b = (const float*)d_in[11];
    const float* gW   = (const float*)d_in[12];
    const float* gb   = (const float*)d_in[13];
    const float* W1   = (const float*)d_in[14];
    const float* b1   = (const float*)d_in[15];
    const float* W2   = (const float*)d_in[16];
    const float* b2   = (const float*)d_in[17];

    bool fuse_out = (out_size >= N_TOK*DMODEL);

    init_kernel<<<1, 1>>>();
    embed_kernel<<<N_TOK, 256>>>(ids, emb, pos);

    for (int l = 0; l < NLAYER; l++){
        mma_gemm<0><<<dim3(QKVD/128, N_TOK/128), 256>>>(
            Wqkv + (size_t)l*DMODEL*QKVD, bqkv + (size_t)l*QKVD, QKVD, DMODEL);
        attn_mma_kernel<<<dim3(TSEQ/64, NHEAD, BATCH), 128>>>(am);
        mma_gemm<1><<<dim3(DMODEL/128, N_TOK/128), 256>>>(
            Wo + (size_t)l*DMODEL*DMODEL, bo + (size_t)l*DMODEL, DMODEL, DMODEL);

        reset_counts_kernel<<<1, 32>>>();
        add_ln_gate_kernel<<<N_TOK, 256>>>(
            ln1g + (size_t)l*DMODEL, ln1b + (size_t)l*DMODEL,
            gW + (size_t)l*DMODEL*NEXP, gb + (size_t)l*NEXP);
        scan_kernel<<<1, 1>>>();
        scatter_kernel<<<(N_TOK + 255)/256, 256>>>();

        mma_gemm<2><<<dim3(HFF/128, CAP/128), 256>>>(
            W1 + (size_t)l*NEXP*DMODEL*HFF, b1 + (size_t)l*NEXP*HFF, HFF, DMODEL);
        mma_gemm<3><<<dim3(DMODEL/128, CAP/128), 256>>>(
            W2 + (size_t)l*NEXP*HFF*DMODEL, b2 + (size_t)l*NEXP*DMODEL, DMODEL, HFF);

        lb_part_kernel<<<NEXP, 256>>>();
        lb_acc_kernel<<<1, 1>>>();

        float* outp = (fuse_out && l == NLAYER-1) ? (float*)d_out : (float*)0;
        add_ln2_kernel<<<N_TOK, 256>>>(
            ln2g + (size_t)l*DMODEL, ln2b + (size_t)l*DMODEL, outp);
    }

    if (fuse_out){
        int extra = out_size - N_TOK*DMODEL;
        if (extra > 0)
            lb_tail_kernel<<<(extra + 255)/256, 256>>>((float*)d_out, out_size);
    } else {
        finalize_kernel<<<(out_size + 255)/256, 256>>>((float*)d_out, out_size);
    }
}

// round 17
// speedup vs baseline: 1.0031x; 1.0031x over previous
#include <cuda_runtime.h>
#include <cuda_bf16.h>
#include <cstdint>
#include <math.h>

#define N_TOK   8192
#define DMODEL  1024
#define QKVD    3072
#define KVW     2048    // K|V packed width (bf16 split storage)
#define NHEAD   16
#define DHEAD   64
#define NEXP    8
#define HFF     4096
#define TSEQ    1024
#define BATCH   8
#define NLAYER  2
#define CAP     17408   // 16384 assignments + 8*128 alignment pad

// ---------------- device scratch ----------------
__device__ float g_x[N_TOK*DMODEL];
__device__ float g_qkv[(size_t)N_TOK*QKVD];          // only Q cols [0,1024) used by attn
__device__ __nv_bfloat16 g_kvh[(size_t)N_TOK*KVW];   // K|V hi (split once in GEMM-0 epilogue)
__device__ __nv_bfloat16 g_kvl[(size_t)N_TOK*KVW];   // K|V lo
__device__ float g_h[N_TOK*DMODEL];
__device__ float g_tmp[N_TOK*DMODEL];
__device__ float g_eout[(size_t)CAP*DMODEL];         // per-slot weighted expert output
__device__ float g_h1[(size_t)CAP*HFF];
__device__ float g_probs[N_TOK*NEXP];
__device__ int   g_tki[N_TOK*2];
__device__ float g_tkw[N_TOK*2];
__device__ int   g_slot[N_TOK*2];                    // token -> slot map
__device__ int   g_counts[NEXP];
__device__ int   g_cursor[NEXP];
__device__ int   g_off[NEXP+1];
__device__ int   g_atok[CAP];
__device__ float g_aw[CAP];
__device__ float g_Pc[NEXP];
__device__ float g_lb;

// ---------------- reductions ----------------
__device__ __forceinline__ float warpRedSum(float v){
#pragma unroll
    for (int o = 16; o; o >>= 1) v += __shfl_xor_sync(0xffffffffu, v, o);
    return v;
}
__device__ float blockRedSum(float v, float* red){
    int lane = threadIdx.x & 31, w = threadIdx.x >> 5, nw = blockDim.x >> 5;
    __syncthreads();
    v = warpRedSum(v);
    if (lane == 0) red[w] = v;
    __syncthreads();
    if (w == 0){
        float x = (lane < nw) ? red[lane] : 0.f;
        x = warpRedSum(x);
        if (lane == 0) red[0] = x;
    }
    __syncthreads();
    return red[0];
}

// ---------------- bf16 helpers (round-nearest split) ----------------
__device__ __forceinline__ unsigned hi2u(float a, float b){
    __nv_bfloat162 h(__float2bfloat16(a), __float2bfloat16(b));
    return *(unsigned*)&h;
}
__device__ __forceinline__ unsigned lo2u(float a, float b){
    float ha = __bfloat162float(__float2bfloat16(a));
    float hb = __bfloat162float(__float2bfloat16(b));
    __nv_bfloat162 l(__float2bfloat16(a - ha), __float2bfloat16(b - hb));
    return *(unsigned*)&l;
}
__device__ __forceinline__ void mma_bf16(float c[4], const unsigned a[4],
                                         unsigned b0, unsigned b1){
    asm volatile("mma.sync.aligned.m16n8k16.row.col.f32.bf16.bf16.f32 "
        "{%0,%1,%2,%3}, {%4,%5,%6,%7}, {%8,%9}, {%0,%1,%2,%3};"
        : "+f"(c[0]), "+f"(c[1]), "+f"(c[2]), "+f"(c[3])
        : "r"(a[0]), "r"(a[1]), "r"(a[2]), "r"(a[3]), "r"(b0), "r"(b1));
}
__device__ __forceinline__ void ldsm4(unsigned r[4], const __nv_bfloat16* p){
    unsigned addr = (unsigned)__cvta_generic_to_shared((void*)p);
    asm volatile("ldmatrix.sync.aligned.m8n8.x4.shared.b16 {%0,%1,%2,%3}, [%4];"
        : "=r"(r[0]), "=r"(r[1]), "=r"(r[2]), "=r"(r[3]) : "r"(addr));
}
__device__ __forceinline__ void ldsm4t(unsigned r[4], const __nv_bfloat16* p){
    unsigned addr = (unsigned)__cvta_generic_to_shared((void*)p);
    asm volatile("ldmatrix.sync.aligned.m8n8.x4.trans.shared.b16 {%0,%1,%2,%3}, [%4];"
        : "=r"(r[0]), "=r"(r[1]), "=r"(r[2]), "=r"(r[3]) : "r"(addr));
}

// ---------------- embedding + positional ----------------
__global__ void embed_kernel(const int* __restrict__ ids,
                             const float* __restrict__ emb,
                             const float* __restrict__ pos){
    int n = blockIdx.x, tid = threadIdx.x;
    int t = n & (TSEQ - 1);
    int id = ids[n];
#pragma unroll
    for (int i = 0; i < 4; i++){
        int d = tid + i * 256;
        g_x[(size_t)n*DMODEL + d] = emb[(size_t)id*DMODEL + d] + pos[(size_t)t*DMODEL + d];
    }
}

// ------- bf16x3 split-fp32 tensor-core GEMM, 128x128 tile, BK=16 -------
// MODE 0: Q (fp32) + K/V (bf16 hi/lo split) = x @ Wqkv + b
// MODE 1: g_tmp = h @ Wo + b
// MODE 2: g_h1  = relu(gather(x) @ W1[e]+b1[e])
// MODE 3: g_eout[slot] = w_slot * (g_h1 @ W2[e] + b2[e])   (plain stores)
#define APAD 24
#define BPAD 136
template<int MODE>
__global__ void __launch_bounds__(256, 2)
mma_gemm(const float* __restrict__ Bmat, const float* __restrict__ biasB,
         int N, int K)
{
    int bn = blockIdx.x * 128;
    int bm = blockIdx.y * 128;
    int tid  = threadIdx.x;
    int warp = tid >> 5, lane = tid & 31;
    int wm = warp >> 1, wn = warp & 1;

    int e = 0;
    if (MODE == 2 || MODE == 3){
        if (bm >= g_off[NEXP]) return;
#pragma unroll
        for (int i = 1; i < NEXP; i++) if (bm >= g_off[i]) e = i;
        Bmat  += (size_t)e * K * N;
        biasB += (size_t)e * N;
    }

    __shared__ __align__(16) __nv_bfloat16 Ah[2][128][APAD];
    __shared__ __align__(16) __nv_bfloat16 Al[2][128][APAD];
    __shared__ __align__(16) __nv_bfloat16 Bh[2][16][BPAD];
    __shared__ __align__(16) __nv_bfloat16 Bl[2][16][BPAD];

    int r0 = tid >> 2, r1 = r0 + 64;
    int k4 = (tid & 3) * 4;
    int kb0 = tid >> 5, kb1 = kb0 + 8;
    int cb  = (tid & 31) * 4;

    const float *Ap0, *Ap1;
    if      (MODE == 0){ Ap0 = &g_x [(size_t)(bm + r0) * DMODEL]; Ap1 = &g_x [(size_t)(bm + r1) * DMODEL]; }
    else if (MODE == 1){ Ap0 = &g_h [(size_t)(bm + r0) * DMODEL]; Ap1 = &g_h [(size_t)(bm + r1) * DMODEL]; }
    else if (MODE == 2){ Ap0 = &g_x [(size_t)g_atok[bm + r0] * DMODEL]; Ap1 = &g_x [(size_t)g_atok[bm + r1] * DMODEL]; }
    else               { Ap0 = &g_h1[(size_t)(bm + r0) * HFF];    Ap1 = &g_h1[(size_t)(bm + r1) * HFF]; }

    const float* Bp0 = Bmat + (size_t)kb0 * N + bn + cb;
    const float* Bp1 = Bmat + (size_t)kb1 * N + bn + cb;

    float acc[2][8][4];
#pragma unroll
    for (int mt = 0; mt < 2; mt++)
#pragma unroll
        for (int nt = 0; nt < 8; nt++)
#pragma unroll
            for (int i = 0; i < 4; i++) acc[mt][nt][i] = 0.f;

    float4 pa0 = *(const float4*)(Ap0 + k4);
    float4 pa1 = *(const float4*)(Ap1 + k4);
    float4 pb0 = *(const float4*)Bp0;
    float4 pb1 = *(const float4*)Bp1;

    {
        *(uint2*)&Ah[0][r0][k4] = make_uint2(hi2u(pa0.x,pa0.y), hi2u(pa0.z,pa0.w));
        *(uint2*)&Al[0][r0][k4] = make_uint2(lo2u(pa0.x,pa0.y), lo2u(pa0.z,pa0.w));
        *(uint2*)&Ah[0][r1][k4] = make_uint2(hi2u(pa1.x,pa1.y), hi2u(pa1.z,pa1.w));
        *(uint2*)&Al[0][r1][k4] = make_uint2(lo2u(pa1.x,pa1.y), lo2u(pa1.z,pa1.w));
        *(uint2*)&Bh[0][kb0][cb] = make_uint2(hi2u(pb0.x,pb0.y), hi2u(pb0.z,pb0.w));
        *(uint2*)&Bl[0][kb0][cb] = make_uint2(lo2u(pb0.x,pb0.y), lo2u(pb0.z,pb0.w));
        *(uint2*)&Bh[0][kb1][cb] = make_uint2(hi2u(pb1.x,pb1.y), hi2u(pb1.z,pb1.w));
        *(uint2*)&Bl[0][kb1][cb] = make_uint2(lo2u(pb1.x,pb1.y), lo2u(pb1.z,pb1.w));
    }
    __syncthreads();

    int arow = (lane & 15), akc = (lane >> 4) * 8;
    int bkr  = (lane & 7) + ((lane >> 3) & 1) * 8;
    int bnc  = wn * 64 + (lane >> 4) * 8;

    int buf = 0;
    for (int k0 = 0; k0 < K; k0 += 16){
        bool more = (k0 + 16 < K);
        if (more){
            pa0 = *(const float4*)(Ap0 + k0 + 16 + k4);
            pa1 = *(const float4*)(Ap1 + k0 + 16 + k4);
            pb0 = *(const float4*)(Bp0 + (size_t)16 * N);
            pb1 = *(const float4*)(Bp1 + (size_t)16 * N);
            Bp0 += (size_t)16 * N; Bp1 += (size_t)16 * N;
        }

        unsigned ah[2][4], al[2][4];
#pragma unroll
        for (int mt = 0; mt < 2; mt++){
            int r = wm*32 + mt*16 + arow;
            ldsm4(ah[mt], &Ah[buf][r][akc]);
            ldsm4(al[mt], &Al[buf][r][akc]);
        }
#pragma unroll
        for (int ng = 0; ng < 4; ng++){
            unsigned bh[4], bl[4];
            ldsm4t(bh, &Bh[buf][bkr][bnc + ng*16]);
            ldsm4t(bl, &Bl[buf][bkr][bnc + ng*16]);
#pragma unroll
            for (int mt = 0; mt < 2; mt++){
                mma_bf16(acc[mt][2*ng  ], ah[mt], bh[0], bh[1]);
                mma_bf16(acc[mt][2*ng  ], ah[mt], bl[0], bl[1]);
                mma_bf16(acc[mt][2*ng  ], al[mt], bh[0], bh[1]);
                mma_bf16(acc[mt][2*ng+1], ah[mt], bh[2], bh[3]);
                mma_bf16(acc[mt][2*ng+1], ah[mt], bl[2], bl[3]);
                mma_bf16(acc[mt][2*ng+1], al[mt], bh[2], bh[3]);
            }
        }

        if (more){
            int nb = buf ^ 1;
            *(uint2*)&Ah[nb][r0][k4] = make_uint2(hi2u(pa0.x,pa0.y), hi2u(pa0.z,pa0.w));
            *(uint2*)&Al[nb][r0][k4] = make_uint2(lo2u(pa0.x,pa0.y), lo2u(pa0.z,pa0.w));
            *(uint2*)&Ah[nb][r1][k4] = make_uint2(hi2u(pa1.x,pa1.y), hi2u(pa1.z,pa1.w));
            *(uint2*)&Al[nb][r1][k4] = make_uint2(lo2u(pa1.x,pa1.y), lo2u(pa1.z,pa1.w));
            *(uint2*)&Bh[nb][kb0][cb] = make_uint2(hi2u(pb0.x,pb0.y), hi2u(pb0.z,pb0.w));
            *(uint2*)&Bl[nb][kb0][cb] = make_uint2(lo2u(pb0.x,pb0.y), lo2u(pb0.z,pb0.w));
            *(uint2*)&Bh[nb][kb1][cb] = make_uint2(hi2u(pb1.x,pb1.y), hi2u(pb1.z,pb1.w));
            *(uint2*)&Bl[nb][kb1][cb] = make_uint2(lo2u(pb1.x,pb1.y), lo2u(pb1.z,pb1.w));
        }
        __syncthreads();
        buf ^= 1;
    }

    int rql = lane >> 2, rqm = lane & 3;
    int c_lo = 2 * rqm;
#pragma unroll
    for (int mt = 0; mt < 2; mt++){
        int grA = bm + wm*32 + mt*16 + rql;
        int grB = grA + 8;
        if (MODE == 3){
            float wA = g_aw[grA], wB = g_aw[grB];
#pragma unroll
            for (int nt = 0; nt < 8; nt++){
                int gc = bn + wn*64 + nt*8 + c_lo;
                float b0 = biasB[gc], b1 = biasB[gc+1];
                *(float2*)&g_eout[(size_t)grA*DMODEL + gc] =
                    make_float2(wA*(acc[mt][nt][0] + b0), wA*(acc[mt][nt][1] + b1));
                *(float2*)&g_eout[(size_t)grB*DMODEL + gc] =
                    make_float2(wB*(acc[mt][nt][2] + b0), wB*(acc[mt][nt][3] + b1));
            }
        } else {
#pragma unroll
            for (int nt = 0; nt < 8; nt++){
                int gc = bn + wn*64 + nt*8 + c_lo;
                float b0 = biasB[gc], b1 = biasB[gc+1];
                float v0 = acc[mt][nt][0] + b0, v1 = acc[mt][nt][1] + b1;
                float v2 = acc[mt][nt][2] + b0, v3 = acc[mt][nt][3] + b1;
                if (MODE == 0){
                    if (gc < DMODEL){   // Q stays fp32
                        g_qkv[(size_t)grA*QKVD + gc] = v0; g_qkv[(size_t)grA*QKVD + gc+1] = v1;
                        g_qkv[(size_t)grB*QKVD + gc] = v2; g_qkv[(size_t)grB*QKVD + gc+1] = v3;
                    } else {            // K/V: split once, store bf16 hi/lo
                        size_t iA = (size_t)grA*KVW + (gc - DMODEL);
                        size_t iB = (size_t)grB*KVW + (gc - DMODEL);
                        *(unsigned*)&g_kvh[iA] = hi2u(v0, v1);
                        *(unsigned*)&g_kvl[iA] = lo2u(v0, v1);
                        *(unsigned*)&g_kvh[iB] = hi2u(v2, v3);
                        *(unsigned*)&g_kvl[iB] = lo2u(v2, v3);
                    }
                } else if (MODE == 1){
                    g_tmp[(size_t)grA*DMODEL + gc] = v0; g_tmp[(size_t)grA*DMODEL + gc+1] = v1;
                    g_tmp[(size_t)grB*DMODEL + gc] = v2; g_tmp[(size_t)grB*DMODEL + gc+1] = v3;
                } else {
                    g_h1[(size_t)grA*HFF + gc]   = fmaxf(v0, 0.f);
                    g_h1[(size_t)grA*HFF + gc+1] = fmaxf(v1, 0.f);
                    g_h1[(size_t)grB*HFF + gc]   = fmaxf(v2, 0.f);
                    g_h1[(size_t)grB*HFF + gc+1] = fmaxf(v3, 0.f);
                }
            }
        }
    }
}

// -------- tensor-core flash attention (bf16x3), 64q x 64k tiles --------
// K/V pre-split by GEMM-0 epilogue: staging is pure uint4 copies.
// __launch_bounds__(128, 4): cap regs at 128 -> 4 CTAs/SM (occ 25%).
__global__ void __launch_bounds__(128, 4)
attn_mma_kernel(const int* __restrict__ amask){
    int qt = gridDim.x - 1 - blockIdx.x;   // big blocks first
    int h = blockIdx.y, b = blockIdx.z;
    int tid = threadIdx.x, warp = tid >> 5, lane = tid & 31;
    int g = lane >> 2, q = lane & 3;
    int qbase = qt * 64;

    __shared__ __align__(16) __nv_bfloat16 Kh[64][72], Kl[64][72];
    __shared__ __align__(16) __nv_bfloat16 Vh[64][72], Vl[64][72];
    __shared__ int AMs[64];

    {
        int row = tid >> 1, c0 = (tid & 1) * 32;
        const float* src = &g_qkv[(size_t)(b*TSEQ + qbase + row)*QKVD + h*DHEAD + c0];
#pragma unroll
        for (int i = 0; i < 8; i++){
            float4 v = *(const float4*)(src + i*4);
            v.x *= 0.125f; v.y *= 0.125f; v.z *= 0.125f; v.w *= 0.125f;
            *(uint2*)&Kh[row][c0 + i*4] = make_uint2(hi2u(v.x,v.y), hi2u(v.z,v.w));
            *(uint2*)&Kl[row][c0 + i*4] = make_uint2(lo2u(v.x,v.y), lo2u(v.z,v.w));
        }
    }
    __syncthreads();

    unsigned qhf[4][4], qlf[4][4];
    {
        int r = warp*16 + (lane & 15);
        int kc = (lane >> 4) * 8;
#pragma unroll
        for (int kk = 0; kk < 4; kk++){
            ldsm4(qhf[kk], &Kh[r][kk*16 + kc]);
            ldsm4(qlf[kk], &Kl[r][kk*16 + kc]);
        }
    }

    float o[8][4];
#pragma unroll
    for (int i = 0; i < 8; i++)
#pragma unroll
        for (int j = 0; j < 4; j++) o[i][j] = 0.f;
    float m0 = -3.0e38f, m1 = -3.0e38f, l0 = 0.f, l1 = 0.f;

    int row0 = qbase + warp*16 + g, row1 = row0 + 8;
    int nrow = lane & 15, nkc = (lane >> 4) * 8;
    int bkr  = (lane & 7) + ((lane >> 3) & 1) * 8;
    int bnc  = (lane >> 4) * 8;

    int ntiles = qt + 1;
    for (int tile = 0; tile < ntiles; tile++){
        int j0 = tile * 64;
        __syncthreads();
        {
            int row = tid >> 1, c0 = (tid & 1) * 32;
            size_t base = (size_t)(b*TSEQ + j0 + row)*KVW + h*DHEAD + c0;
#pragma unroll
            for (int i = 0; i < 4; i++){
                *(uint4*)&Kh[row][c0+i*8] = *(const uint4*)&g_kvh[base + i*8];
                *(uint4*)&Kl[row][c0+i*8] = *(const uint4*)&g_kvl[base + i*8];
                *(uint4*)&Vh[row][c0+i*8] = *(const uint4*)&g_kvh[base + DMODEL + i*8];
                *(uint4*)&Vl[row][c0+i*8] = *(const uint4*)&g_kvl[base + DMODEL + i*8];
            }
            if (tid < 64) AMs[tid] = amask[b*TSEQ + j0 + tid];
        }
        __syncthreads();

        float st[8][4];
#pragma unroll
        for (int i = 0; i < 8; i++)
#pragma unroll
            for (int j = 0; j < 4; j++) st[i][j] = 0.f;
#pragma unroll
        for (int nt2 = 0; nt2 < 4; nt2++){
#pragma unroll
            for (int kk = 0; kk < 4; kk++){
                unsigned kh[4], kl[4];
                ldsm4(kh, &Kh[nt2*16 + nrow][kk*16 + nkc]);
                ldsm4(kl, &Kl[nt2*16 + nrow][kk*16 + nkc]);
                mma_bf16(st[2*nt2  ], qhf[kk], kh[0], kh[2]);
                mma_bf16(st[2*nt2  ], qhf[kk], kl[0], kl[2]);
                mma_bf16(st[2*nt2  ], qlf[kk], kh[0], kh[2]);
                mma_bf16(st[2*nt2+1], qhf[kk], kh[1], kh[3]);
                mma_bf16(st[2*nt2+1], qhf[kk], kl[1], kl[3]);
                mma_bf16(st[2*nt2+1], qlf[kk], kh[1], kh[3]);
            }
        }

#pragma unroll
        for (int nt = 0; nt < 8; nt++){
            int lc = nt*8 + 2*q;
            int c  = j0 + lc;
            int a0 = AMs[lc], a1 = AMs[lc+1];
            if (c   > row0 || !a0) st[nt][0] = -1e9f;
            if (c+1 > row0 || !a1) st[nt][1] = -1e9f;
            if (c   > row1 || !a0) st[nt][2] = -1e9f;
            if (c+1 > row1 || !a1) st[nt][3] = -1e9f;
        }

        float mx0 = -3.0e38f, mx1 = -3.0e38f;
#pragma unroll
        for (int nt = 0; nt < 8; nt++){
            mx0 = fmaxf(mx0, fmaxf(st[nt][0], st[nt][1]));
            mx1 = fmaxf(mx1, fmaxf(st[nt][2], st[nt][3]));
        }
#pragma unroll
        for (int off = 1; off <= 2; off <<= 1){
            mx0 = fmaxf(mx0, __shfl_xor_sync(0xffffffffu, mx0, off));
            mx1 = fmaxf(mx1, __shfl_xor_sync(0xffffffffu, mx1, off));
        }
        float mn0 = fmaxf(m0, mx0), mn1 = fmaxf(m1, mx1);
        float sc0 = __expf(m0 - mn0), sc1 = __expf(m1 - mn1);
        float ls0 = 0.f, ls1 = 0.f;
#pragma unroll
        for (int nt = 0; nt < 8; nt++){
            st[nt][0] = __expf(st[nt][0] - mn0);
            st[nt][1] = __expf(st[nt][1] - mn0);
            st[nt][2] = __expf(st[nt][2] - mn1);
            st[nt][3] = __expf(st[nt][3] - mn1);
            ls0 += st[nt][0] + st[nt][1];
            ls1 += st[nt][2] + st[nt][3];
        }
#pragma unroll
        for (int off = 1; off <= 2; off <<= 1){
            ls0 += __shfl_xor_sync(0xffffffffu, ls0, off);
            ls1 += __shfl_xor_sync(0xffffffffu, ls1, off);
        }
        l0 = l0*sc0 + ls0;  l1 = l1*sc1 + ls1;
#pragma unroll
        for (int nt = 0; nt < 8; nt++){
            o[nt][0] *= sc0; o[nt][1] *= sc0;
            o[nt][2] *= sc1; o[nt][3] *= sc1;
        }
        m0 = mn0; m1 = mn1;

#pragma unroll
        for (int kk2 = 0; kk2 < 4; kk2++){
            unsigned ph[4], pl[4];
            ph[0] = hi2u(st[2*kk2  ][0], st[2*kk2  ][1]);
            ph[1] = hi2u(st[2*kk2  ][2], st[2*kk2  ][3]);
            ph[2] = hi2u(st[2*kk2+1][0], st[2*kk2+1][1]);
            ph[3] = hi2u(st[2*kk2+1][2], st[2*kk2+1][3]);
            pl[0] = lo2u(st[2*kk2  ][0], st[2*kk2  ][1]);
            pl[1] = lo2u(st[2*kk2  ][2], st[2*kk2  ][3]);
            pl[2] = lo2u(st[2*kk2+1][0], st[2*kk2+1][1]);
            pl[3] = lo2u(st[2*kk2+1][2], st[2*kk2+1][3]);
#pragma unroll
            for (int dt2 = 0; dt2 < 4; dt2++){
                unsigned vh[4], vl[4];
                ldsm4t(vh, &Vh[kk2*16 + bkr][dt2*16 + bnc]);
                ldsm4t(vl, &Vl[kk2*16 + bkr][dt2*16 + bnc]);
                mma_bf16(o[2*dt2  ], ph, vh[0], vh[1]);
                mma_bf16(o[2*dt2  ], ph, vl[0], vl[1]);
                mma_bf16(o[2*dt2  ], pl, vh[0], vh[1]);
                mma_bf16(o[2*dt2+1], ph, vh[2], vh[3]);
                mma_bf16(o[2*dt2+1], ph, vl[2], vl[3]);
                mma_bf16(o[2*dt2+1], pl, vh[2], vh[3]);
            }
        }
    }

    float inv0 = 1.f / l0, inv1 = 1.f / l1;
    size_t n0 = (size_t)(b*TSEQ + row0)*DMODEL + h*DHEAD;
    size_t n1 = (size_t)(b*TSEQ + row1)*DMODEL + h*DHEAD;
#pragma unroll
    for (int dt = 0; dt < 8; dt++){
        int c = dt*8 + 2*q;
        *(float2*)&g_h[n0 + c] = make_float2(o[dt][0]*inv0, o[dt][1]*inv0);
        *(float2*)&g_h[n1 + c] = make_float2(o[dt][2]*inv1, o[dt][3]*inv1);
    }
}

// ------- fused: x = LN(x + g_tmp); then router (gate+softmax+top2) -------
__global__ void add_ln_gate_kernel(const float* __restrict__ g,
                                   const float* __restrict__ bta,
                                   const float* __restrict__ W,
                                   const float* __restrict__ bb){
    int n = blockIdx.x, tid = threadIdx.x;
    __shared__ float red[32];
    __shared__ float sred[NEXP][256];
    float v[4];
    float s = 0.f;
#pragma unroll
    for (int i = 0; i < 4; i++){
        int d = tid + i*256;
        v[i] = g_x[(size_t)n*DMODEL + d] + g_tmp[(size_t)n*DMODEL + d];
        s += v[i];
    }
    float mean = blockRedSum(s, red) * (1.f/DMODEL);
    float vs = 0.f;
#pragma unroll
    for (int i = 0; i < 4; i++){ float dd = v[i] - mean; vs += dd*dd; }
    float var = blockRedSum(vs, red) * (1.f/DMODEL);
    float r = rsqrtf(var + 1e-5f);
    float y[4];
#pragma unroll
    for (int i = 0; i < 4; i++){
        int d = tid + i*256;
        y[i] = (v[i] - mean)*r*g[d] + bta[d];
        g_x[(size_t)n*DMODEL + d] = y[i];
    }
    // ---- router on the registers we already hold ----
    float acc[NEXP];
#pragma unroll
    for (int e = 0; e < NEXP; e++) acc[e] = 0.f;
#pragma unroll
    for (int i = 0; i < 4; i++){
        int d = tid + i*256;
#pragma unroll
        for (int e = 0; e < NEXP; e++) acc[e] += y[i] * W[d*NEXP + e];
    }
#pragma unroll
    for (int e = 0; e < NEXP; e++) sred[e][tid] = acc[e];
    __syncthreads();
    for (int st = 128; st > 0; st >>= 1){
        if (tid < st){
#pragma unroll
            for (int e = 0; e < NEXP; e++) sred[e][tid] += sred[e][tid + st];
        }
        __syncthreads();
    }
    if (tid == 0){
        float lg[NEXP], mx = -3e38f;
#pragma unroll
        for (int e = 0; e < NEXP; e++){ lg[e] = sred[e][0] + bb[e]; mx = fmaxf(mx, lg[e]); }
        float ss = 0.f, p[NEXP];
#pragma unroll
        for (int e = 0; e < NEXP; e++){ p[e] = __expf(lg[e] - mx); ss += p[e]; }
        float invs = 1.f / ss;
#pragma unroll
        for (int e = 0; e < NEXP; e++){ p[e] *= invs; g_probs[n*NEXP + e] = p[e]; }
        int i1 = 0;
#pragma unroll
        for (int e = 1; e < NEXP; e++) if (p[e] > p[i1]) i1 = e;
        int i2 = (i1 == 0) ? 1 : 0;
#pragma unroll
        for (int e = 0; e < NEXP; e++) if (e != i1 && p[e] > p[i2]) i2 = e;
        float sw = p[i1] + p[i2];
        g_tki[n*2]   = i1; g_tki[n*2+1] = i2;
        g_tkw[n*2]   = p[i1] / sw;
        g_tkw[n*2+1] = p[i2] / sw;
        atomicAdd(&g_counts[i1], 1);
        atomicAdd(&g_counts[i2], 1);
    }
}

// ------- x = LN(x + gather2(g_eout)); optionally also write d_out -------
__global__ void add_ln2_kernel(const float* __restrict__ g,
                               const float* __restrict__ bta,
                               float* __restrict__ out){
    int n = blockIdx.x, tid = threadIdx.x;
    __shared__ float red[32];
    float v[4];
    float s = 0.f;
    size_t s0 = (size_t)g_slot[n*2]     * DMODEL;
    size_t s1 = (size_t)g_slot[n*2 + 1] * DMODEL;
#pragma unroll
    for (int i = 0; i < 4; i++){
        int d = tid + i*256;
        v[i] = g_x[(size_t)n*DMODEL + d] + (g_eout[s0 + d] + g_eout[s1 + d]);
        s += v[i];
    }
    float mean = blockRedSum(s, red) * (1.f/DMODEL);
    float vs = 0.f;
#pragma unroll
    for (int i = 0; i < 4; i++){ float dd = v[i] - mean; vs += dd*dd; }
    float var = blockRedSum(vs, red) * (1.f/DMODEL);
    float r = rsqrtf(var + 1e-5f);
#pragma unroll
    for (int i = 0; i < 4; i++){
        int d = tid + i*256;
        float val = (v[i] - mean)*r*g[d] + bta[d];
        size_t idx = (size_t)n*DMODEL + d;
        g_x[idx] = val;
        if (out) out[idx] = val;
    }
}

// ---------------- tiny per-layer reset (counts/cursor only) ----------------
__global__ void reset_counts_kernel(){
    int i = threadIdx.x;
    if (i < NEXP){ g_counts[i] = 0; g_cursor[i] = 0; }
}

__global__ void scan_kernel(){
    if (threadIdx.x == 0){
        int o = 0;
        for (int e = 0; e < NEXP; e++){
            g_off[e] = o;
            o += (g_counts[e] + 127) & ~127;
        }
        g_off[NEXP] = o;
    }
}

__global__ void scatter_kernel(){
    int n = blockIdx.x * blockDim.x + threadIdx.x;
    if (n >= N_TOK) return;
#pragma unroll
    for (int k = 0; k < 2; k++){
        int e = g_tki[n*2 + k];
        int pos = atomicAdd(&g_cursor[e], 1);
        int slot = g_off[e] + pos;
        g_atok[slot] = n;
        g_aw[slot]   = g_tkw[n*2 + k];
        g_slot[n*2 + k] = slot;
    }
}

// ---------------- load-balance loss ----------------
__global__ void lb_part_kernel(){
    int e = blockIdx.x, tid = threadIdx.x;
    __shared__ float red[32];
    float s = 0.f;
    for (int n = tid; n < N_TOK; n += 256) s += g_probs[n*NEXP + e];
    float tot = blockRedSum(s, red);
    if (tid == 0)
        g_Pc[e] = (float)NEXP * ((float)g_counts[e] / (float)N_TOK) * (tot / (float)N_TOK);
}
__global__ void lb_acc_kernel(){
    if (threadIdx.x == 0){
        float s = 0.f;
        for (int e = 0; e < NEXP; e++) s += g_Pc[e];
        g_lb += s;
    }
}
__global__ void init_kernel(){ g_lb = 0.f; }

// ---------------- output tail (lb scalar) / fallback full copy ----------------
__global__ void lb_tail_kernel(float* __restrict__ out, int out_size){
    int i = N_TOK*DMODEL + blockIdx.x * blockDim.x + threadIdx.x;
    if (i < out_size) out[i] = g_lb;
}
__global__ void finalize_kernel(float* __restrict__ out, int out_size){
    int i = blockIdx.x * blockDim.x + threadIdx.x;
    if (i >= out_size) return;
    if (i < N_TOK*DMODEL) out[i] = g_x[i];
    else                  out[i] = g_lb;
}

// ---------------- host orchestration ----------------
extern "C" void kernel_launch(void* const* d_in, const int* in_sizes, int n_in,
                              void* d_out, int out_size)
{
    const int*   ids  = (const int*)  d_in[0];
    const int*   am   = (const int*)  d_in[1];
    const float* emb  = (const float*)d_in[2];
    const float* pos  = (const float*)d_in[3];
    const float* Wqkv = (const float*)d_in[4];
    const float* bqkv = (const float*)d_in[5];
    const float* Wo   = (const float*)d_in[6];
    const float* bo   = (const float*)d_in[7];
    const float* ln1g = (const float*)d_in[8];
    const float* ln1b = (const float*)d_in[9];
    const float* ln2g = (const float*)d_in[10];
    const float* ln2b = (const float*)d_in[11];
    const float* gW   = (const float*)d_in[12];
    const float* gb   = (const float*)d_in[13];
    const float* W1   = (const float*)d_in[14];
    const float* b1   = (const float*)d_in[15];
    const float* W2   = (const float*)d_in[16];
    const float* b2   = (const float*)d_in[17];

    bool fuse_out = (out_size >= N_TOK*DMODEL);

    init_kernel<<<1, 1>>>();
    embed_kernel<<<N_TOK, 256>>>(ids, emb, pos);

    for (int l = 0; l < NLAYER; l++){
        mma_gemm<0><<<dim3(QKVD/128, N_TOK/128), 256>>>(
            Wqkv + (size_t)l*DMODEL*QKVD, bqkv + (size_t)l*QKVD, QKVD, DMODEL);
        attn_mma_kernel<<<dim3(TSEQ/64, NHEAD, BATCH), 128>>>(am);
        mma_gemm<1><<<dim3(DMODEL/128, N_TOK/128), 256>>>(
            Wo + (size_t)l*DMODEL*DMODEL, bo + (size_t)l*DMODEL, DMODEL, DMODEL);

        reset_counts_kernel<<<1, 32>>>();
        add_ln_gate_kernel<<<N_TOK, 256>>>(
            ln1g + (size_t)l*DMODEL, ln1b + (size_t)l*DMODEL,
            gW + (size_t)l*DMODEL*NEXP, gb + (size_t)l*NEXP);
        scan_kernel<<<1, 1>>>();
        scatter_kernel<<<(N_TOK + 255)/256, 256>>>();

        mma_gemm<2><<<dim3(HFF/128, CAP/128), 256>>>(
            W1 + (size_t)l*NEXP*DMODEL*HFF, b1 + (size_t)l*NEXP*HFF, HFF, DMODEL);
        mma_gemm<3><<<dim3(DMODEL/128, CAP/128), 256>>>(
            W2 + (size_t)l*NEXP*HFF*DMODEL, b2 + (size_t)l*NEXP*DMODEL, DMODEL, HFF);

        lb_part_kernel<<<NEXP, 256>>>();
        lb_acc_kernel<<<1, 1>>>();

        float* outp = (fuse_out && l == NLAYER-1) ? (float*)d_out : (float*)0;
        add_ln2_kernel<<<N_TOK, 256>>>(
            ln2g + (size_t)l*DMODEL, ln2b + (size_t)l*DMODEL, outp);
    }

    if (fuse_out){
        int extra = out_size - N_TOK*DMODEL;
        if (extra > 0)
            lb_tail_kernel<<<(extra + 255)/256, 256>>>((float*)d_out, out_size);
    } else {
        finalize_kernel<<<(out_size + 255)/256, 256>>>((float*)d_out, out_size);
    }
}